// round 16
// baseline (speedup 1.0000x reference)
#include <cuda_runtime.h>
#include <cuda_fp16.h>
#include <cstdint>

#define MAXN 50000
#define MAXN_PAD 50176              // 128-aligned: GEMM tiles read padded rows unguarded
#define MAXE 1600000
#define DMODEL 256
#define FIN 128
#define NGRAPH 128

#define HG_PAD 40                   // smem row stride (halves): 80B, conflict-friendly
#define HG_STAGE (128 * HG_PAD)
#define HG_SMEM (3 * 2 * HG_STAGE * 2)  // 61440 B: 3 stages x (A+B) x fp16

// ---------------- device scratch (allocation-free rule: __device__ globals) ----
__device__ __half g_x16[(size_t)MAXN_PAD * FIN];
__device__ __half g_h1[(size_t)MAXN_PAD * FIN];
__device__ __half g_h2[(size_t)MAXN_PAD * FIN];
__device__ __half g_f16a[(size_t)MAXN_PAD * DMODEL];
__device__ __half g_f16b[(size_t)MAXN_PAD * DMODEL];
__device__ __half g_w16[128 * 256 + 3 * 256 * 256];  // sg_w^T, gcn_w[i]^T, fp16 [n][k]
__device__ float  g_dinv[MAXN];
__device__ int    g_deg[MAXN];
__device__ int    g_rowptr[MAXN + 1];
__device__ int    g_fill[MAXN];
__device__ int    g_csrc[MAXE];       // CSR (by dst): src index only (weights factored)
__device__ int    g_blocksum[64];
__device__ int    g_blockoff[64];
__device__ float  g_pool[NGRAPH * DMODEL];
__device__ int    g_is64;

// ---------------- dtype sniffing (int64 vs int32 edge_index) -------------------
__global__ void detect_dtype(const unsigned int* __restrict__ words) {
    __shared__ int nz;
    if (threadIdx.x == 0) nz = 0;
    __syncthreads();
    if (words[2 * threadIdx.x + 1] != 0u) atomicOr(&nz, 1);
    __syncthreads();
    if (threadIdx.x == 0) g_is64 = (nz == 0) ? 1 : 0;
}

__device__ __forceinline__ int ld_idx(const void* p, long long i, int is64) {
    return is64 ? (int)((const long long*)p)[i] : ((const int*)p)[i];
}

// ---------------- edge preprocessing / CSR build --------------------------------
__global__ void init_misc(int n) {
    int i = blockIdx.x * blockDim.x + threadIdx.x;
    if (i < n) g_deg[i] = 1;
    if (i < NGRAPH * DMODEL) g_pool[i] = 0.f;
}

__global__ void count_deg(const void* __restrict__ ei, int e) {
    int i = blockIdx.x * blockDim.x + threadIdx.x;
    if (i >= e) return;
    int d = ld_idx(ei, (long long)e + i, g_is64);
    atomicAdd(&g_deg[d], 1);
}

__global__ void scan_block_sums(int n) {
    __shared__ int sm[1024];
    int i = blockIdx.x * 1024 + threadIdx.x;
    int deg = (i < n) ? g_deg[i] : 1;
    if (i < n) g_dinv[i] = rsqrtf((float)deg);
    sm[threadIdx.x] = (i < n) ? (deg - 1) : 0;
    __syncthreads();
    for (int off = 512; off > 0; off >>= 1) {
        if (threadIdx.x < off) sm[threadIdx.x] += sm[threadIdx.x + off];
        __syncthreads();
    }
    if (threadIdx.x == 0) g_blocksum[blockIdx.x] = sm[0];
}

__global__ void scan_offsets(int nblocks, int n) {
    if (threadIdx.x == 0) {
        int c = 0;
        for (int b = 0; b < nblocks; b++) { g_blockoff[b] = c; c += g_blocksum[b]; }
        g_rowptr[n] = c;
    }
}

__global__ void scan_final(int n) {
    __shared__ int sm[1024];
    int i = blockIdx.x * 1024 + threadIdx.x;
    int v = (i < n) ? (g_deg[i] - 1) : 0;
    sm[threadIdx.x] = v;
    __syncthreads();
    for (int off = 1; off < 1024; off <<= 1) {
        int t = (threadIdx.x >= off) ? sm[threadIdx.x - off] : 0;
        __syncthreads();
        sm[threadIdx.x] += t;
        __syncthreads();
    }
    if (i < n) {
        int excl = g_blockoff[blockIdx.x] + sm[threadIdx.x] - v;
        g_rowptr[i] = excl;
        g_fill[i] = excl;
    }
}

__global__ void build_csr(const void* __restrict__ ei, int e) {
    int i = blockIdx.x * blockDim.x + threadIdx.x;
    if (i >= e) return;
    int is64 = g_is64;
    int s = ld_idx(ei, i, is64);
    int d = ld_idx(ei, (long long)e + i, is64);
    int pos = atomicAdd(&g_fill[d], 1);
    g_csrc[pos] = s;
}

// ---------------- fp32 -> fp16 converts -----------------------------------------
__global__ void cvt_scale_half(const float* __restrict__ x, __half* __restrict__ o,
                               int n) {
    long long i = (long long)blockIdx.x * blockDim.x + threadIdx.x;
    if (i >= (long long)n * (FIN / 4)) return;
    int v = (int)(i >> 5);
    float dv = g_dinv[v];
    float4 t = ((const float4*)x)[i];
    __half2 a = __floats2half2_rn(dv * t.x, dv * t.y);
    __half2 b = __floats2half2_rn(dv * t.z, dv * t.w);
    uint2 u;
    u.x = *(unsigned int*)&a;
    u.y = *(unsigned int*)&b;
    ((uint2*)o)[i] = u;
}

__global__ void cvt_weights(const float* __restrict__ sg_w,
                            const float* __restrict__ gcn_w) {
    int idx = blockIdx.x * blockDim.x + threadIdx.x;
    if (idx < 128 * 256) {
        int k = idx >> 8, nn = idx & 255;
        g_w16[nn * 128 + k] = __float2half_rn(sg_w[idx]);
    } else if (idx < 128 * 256 + 3 * 256 * 256) {
        int j = idx - 128 * 256;
        int i = j >> 16, rem = j & 65535;
        int k = rem >> 8, nn = rem & 255;
        g_w16[128 * 256 + i * 65536 + nn * 256 + k] = __float2half_rn(gcn_w[j]);
    }
}

// ---------------- fused gather propagation (factored normalization) -------------
// Input rows pre-scaled: in'[v] = dinv[v]*in[v]. acc = in'[node] + sum in'[src].
// POST=1: scale dinv; POST=2: scale dinv^2. POOL=1: red.add into g_pool[batch].
// SUB=16 lanes per node for both F; each lane owns PL=F/16 features
// (1 or 2 independent 16B __ldg per edge -> deep load batching).
template <int F, int POST, int RELUB, int POOL>
__global__ __launch_bounds__(256) void prop_gather(
    const __half* __restrict__ x, __half* __restrict__ out,
    const float* __restrict__ bias, const void* __restrict__ batch, int n) {
    constexpr int SUB = 16;
    constexpr int PL = F / SUB;            // floats per lane: 8 (F=128) or 16 (F=256)
    constexpr int V4 = PL / 8;             // uint4 loads per lane: 1 or 2
    int gt = blockIdx.x * blockDim.x + threadIdx.x;
    int node = gt >> 4;
    if (node >= n) return;
    int sl = threadIdx.x & (SUB - 1);
    unsigned mask = 0xffffu << (threadIdx.x & 16);
    const uint4* __restrict__ xr = (const uint4*)x;

    float acc[PL];

#define GATHER_ROW(srow)                                                         \
    do {                                                                         \
        _Pragma("unroll")                                                        \
        for (int q_ = 0; q_ < V4; q_++) {                                        \
            uint4 u_ = __ldg(xr + (size_t)(srow) * (F / 8) + sl * V4 + q_);      \
            float2 f0_ = __half22float2(*(__half2*)&u_.x);                       \
            float2 f1_ = __half22float2(*(((__half2*)&u_.x) + 1));               \
            float2 f2_ = __half22float2(*(__half2*)&u_.z);                       \
            float2 f3_ = __half22float2(*(((__half2*)&u_.z) + 1));               \
            acc[q_ * 8 + 0] += f0_.x; acc[q_ * 8 + 1] += f0_.y;                  \
            acc[q_ * 8 + 2] += f1_.x; acc[q_ * 8 + 3] += f1_.y;                  \
            acc[q_ * 8 + 4] += f2_.x; acc[q_ * 8 + 5] += f2_.y;                  \
            acc[q_ * 8 + 6] += f3_.x; acc[q_ * 8 + 7] += f3_.y;                  \
        }                                                                        \
    } while (0)

#pragma unroll
    for (int q = 0; q < PL; q++) acc[q] = 0.f;
    GATHER_ROW(node);  // self-loop (already pre-scaled)

    int beg = g_rowptr[node], end = g_rowptr[node + 1];
    int b = beg;
    for (; b + SUB <= end; b += SUB) {
        int sj = __ldg(g_csrc + b + sl);
#pragma unroll
        for (int k = 0; k < SUB; k++) {
            int s = __shfl_sync(mask, sj, k, SUB);
            GATHER_ROW(s);
        }
    }
    int rem = end - b;
    if (rem > 0) {
        int sj = 0;
        if (sl < rem) sj = __ldg(g_csrc + b + sl);
        for (int k = 0; k < rem; k++) {
            int s = __shfl_sync(mask, sj, k, SUB);
            GATHER_ROW(s);
        }
    }
#undef GATHER_ROW

    float dv = g_dinv[node];
    float scale = (POST == 2) ? dv * dv : dv;
#pragma unroll
    for (int q = 0; q < PL; q++) acc[q] *= scale;

    if (RELUB) {
#pragma unroll
        for (int q = 0; q < PL / 4; q++) {
            float4 bb = *(const float4*)(bias + sl * PL + q * 4);
            acc[q * 4 + 0] = fmaxf(acc[q * 4 + 0] + bb.x, 0.f);
            acc[q * 4 + 1] = fmaxf(acc[q * 4 + 1] + bb.y, 0.f);
            acc[q * 4 + 2] = fmaxf(acc[q * 4 + 2] + bb.z, 0.f);
            acc[q * 4 + 3] = fmaxf(acc[q * 4 + 3] + bb.w, 0.f);
        }
    }

    if (POOL) {
        int g = ld_idx(batch, node, g_is64);
        float* dst = g_pool + (size_t)g * DMODEL + sl * PL;
#pragma unroll
        for (int q = 0; q < PL / 4; q++) {
            asm volatile("red.global.add.v4.f32 [%0], {%1, %2, %3, %4};"
                         :: "l"(dst + q * 4), "f"(acc[q * 4 + 0]), "f"(acc[q * 4 + 1]),
                            "f"(acc[q * 4 + 2]), "f"(acc[q * 4 + 3])
                         : "memory");
        }
    } else {
#pragma unroll
        for (int q = 0; q < V4; q++) {
            uint4 u;
            __half2 h0 = __floats2half2_rn(acc[q * 8 + 0], acc[q * 8 + 1]);
            __half2 h1 = __floats2half2_rn(acc[q * 8 + 2], acc[q * 8 + 3]);
            __half2 h2 = __floats2half2_rn(acc[q * 8 + 4], acc[q * 8 + 5]);
            __half2 h3 = __floats2half2_rn(acc[q * 8 + 6], acc[q * 8 + 7]);
            u.x = *(unsigned int*)&h0; u.y = *(unsigned int*)&h1;
            u.z = *(unsigned int*)&h2; u.w = *(unsigned int*)&h3;
            ((uint4*)out)[(size_t)node * (F / 8) + sl * V4 + q] = u;
        }
    }
}

// ---------------- cp.async helpers ----------------------------------------------
__device__ __forceinline__ void cp_async16(void* smem, const void* gmem) {
    unsigned saddr;
    asm("{ .reg .u64 t; cvta.to.shared.u64 t, %1; cvt.u32.u64 %0, t; }"
        : "=r"(saddr) : "l"(smem));
    asm volatile("cp.async.cg.shared.global [%0], [%1], 16;"
                 :: "r"(saddr), "l"(gmem) : "memory");
}

// ---------------- fp16 HMMA GEMM, 3-stage cp.async pipeline (dynamic smem) ------
__global__ __launch_bounds__(256) void hgemm128(
    const __half* __restrict__ A, const __half* __restrict__ Bt,
    const float* __restrict__ bias, __half* __restrict__ C,
    int M, int K, int N, int relu, int scale) {
    extern __shared__ __align__(16) __half smem[];
    __half* Asm = smem;
    __half* Bsm = smem + 3 * HG_STAGE;
#define AS(st, r, c) Asm[(st) * HG_STAGE + (r) * HG_PAD + (c)]
#define BS(st, r, c) Bsm[(st) * HG_STAGE + (r) * HG_PAD + (c)]
    int tid = threadIdx.x;
    int warp = tid >> 5, lane = tid & 31;
    int wm = warp >> 1, wn = warp & 1;
    int row0 = blockIdx.y * 128, col0 = blockIdx.x * 128;
    int gid = lane >> 2, tig = lane & 3;

    float acc[2][8][4];
#pragma unroll
    for (int i = 0; i < 2; i++)
#pragma unroll
        for (int j = 0; j < 8; j++)
#pragma unroll
            for (int q = 0; q < 4; q++) acc[i][j][q] = 0.f;

    int fr = tid >> 2, fc = (tid & 3) * 8;
    const __half* Ap = A + (size_t)(row0 + fr) * K + fc;
    const __half* Ap2 = A + (size_t)(row0 + fr + 64) * K + fc;
    const __half* Bp = Bt + (size_t)(col0 + fr) * K + fc;
    const __half* Bp2 = Bt + (size_t)(col0 + fr + 64) * K + fc;

    int T = K >> 5;
#pragma unroll
    for (int s = 0; s < 2; s++) {
        if (s < T) {
            int kk = s * 32;
            cp_async16(&AS(s, fr, fc), Ap + kk);
            cp_async16(&AS(s, fr + 64, fc), Ap2 + kk);
            cp_async16(&BS(s, fr, fc), Bp + kk);
            cp_async16(&BS(s, fr + 64, fc), Bp2 + kk);
        }
        asm volatile("cp.async.commit_group;");
    }

    for (int t = 0; t < T; t++) {
        if (t + 2 < T) {
            int k2 = (t + 2) * 32;
            int st2 = (t + 2) % 3;
            cp_async16(&AS(st2, fr, fc), Ap + k2);
            cp_async16(&AS(st2, fr + 64, fc), Ap2 + k2);
            cp_async16(&BS(st2, fr, fc), Bp + k2);
            cp_async16(&BS(st2, fr + 64, fc), Bp2 + k2);
        }
        asm volatile("cp.async.commit_group;");
        asm volatile("cp.async.wait_group 2;");
        __syncthreads();
        int st = t % 3;
#pragma unroll
        for (int ks = 0; ks < 2; ks++) {
            int kk = ks * 16;
            unsigned int af[2][4];
#pragma unroll
            for (int mt = 0; mt < 2; mt++) {
                int r = wm * 32 + mt * 16 + gid;
                af[mt][0] = *(unsigned int*)&AS(st, r, kk + 2 * tig);
                af[mt][1] = *(unsigned int*)&AS(st, r + 8, kk + 2 * tig);
                af[mt][2] = *(unsigned int*)&AS(st, r, kk + 2 * tig + 8);
                af[mt][3] = *(unsigned int*)&AS(st, r + 8, kk + 2 * tig + 8);
            }
            unsigned int bf[8][2];
#pragma unroll
            for (int nt = 0; nt < 8; nt++) {
                int c = wn * 64 + nt * 8 + gid;
                bf[nt][0] = *(unsigned int*)&BS(st, c, kk + 2 * tig);
                bf[nt][1] = *(unsigned int*)&BS(st, c, kk + 2 * tig + 8);
            }
#pragma unroll
            for (int mt = 0; mt < 2; mt++)
#pragma unroll
                for (int nt = 0; nt < 8; nt++) {
                    asm volatile(
                        "mma.sync.aligned.m16n8k16.row.col.f32.f16.f16.f32 "
                        "{%0,%1,%2,%3}, {%4,%5,%6,%7}, {%8,%9}, {%0,%1,%2,%3};"
                        : "+f"(acc[mt][nt][0]), "+f"(acc[mt][nt][1]),
                          "+f"(acc[mt][nt][2]), "+f"(acc[mt][nt][3])
                        : "r"(af[mt][0]), "r"(af[mt][1]), "r"(af[mt][2]), "r"(af[mt][3]),
                          "r"(bf[nt][0]), "r"(bf[nt][1]));
                }
        }
        __syncthreads();
    }
#undef AS
#undef BS

#pragma unroll
    for (int mt = 0; mt < 2; mt++) {
        int r1 = row0 + wm * 32 + mt * 16 + gid;
        int r2 = r1 + 8;
        float s1 = 1.f, s2 = 1.f;
        if (scale) {
            s1 = (r1 < M) ? g_dinv[r1] : 0.f;
            s2 = (r2 < M) ? g_dinv[r2] : 0.f;
        }
#pragma unroll
        for (int nt = 0; nt < 8; nt++) {
            int c = col0 + wn * 64 + nt * 8 + 2 * tig;
            float bx = 0.f, by = 0.f;
            if (bias) { bx = bias[c]; by = bias[c + 1]; }
            float2 v1 = make_float2((acc[mt][nt][0] + bx) * s1, (acc[mt][nt][1] + by) * s1);
            float2 v2 = make_float2((acc[mt][nt][2] + bx) * s2, (acc[mt][nt][3] + by) * s2);
            if (relu) {
                v1.x = fmaxf(v1.x, 0.f); v1.y = fmaxf(v1.y, 0.f);
                v2.x = fmaxf(v2.x, 0.f); v2.y = fmaxf(v2.y, 0.f);
            }
            if (r1 < M) *(__half2*)(C + (size_t)r1 * N + c) = __floats2half2_rn(v1.x, v1.y);
            if (r2 < M) *(__half2*)(C + (size_t)r2 * N + c) = __floats2half2_rn(v2.x, v2.y);
        }
    }
}

// ---------------- fused MLP head (exact fp32): pool -> fc1 -> fc2 -> fc3 --------
__global__ __launch_bounds__(256) void mlp_head(
    const float* __restrict__ fc1_w, const float* __restrict__ fc1_b,
    const float* __restrict__ fc2_w, const float* __restrict__ fc2_b,
    const float* __restrict__ fc3_w, const float* __restrict__ fc3_b,
    float* __restrict__ out) {
    __shared__ float sp[DMODEL];
    __shared__ float sm1[DMODEL];
    __shared__ float sm2[DMODEL / 2];
    int g = blockIdx.x;
    int tid = threadIdx.x;

    sp[tid] = g_pool[g * DMODEL + tid];
    __syncthreads();

    float a = fc1_b[tid];
#pragma unroll 8
    for (int k = 0; k < DMODEL; k++)
        a = fmaf(sp[k], fc1_w[k * DMODEL + tid], a);
    sm1[tid] = fmaxf(a, 0.f);
    __syncthreads();

    if (tid < DMODEL / 2) {
        float b = fc2_b[tid];
#pragma unroll 8
        for (int k = 0; k < DMODEL; k++)
            b = fmaf(sm1[k], fc2_w[k * (DMODEL / 2) + tid], b);
        sm2[tid] = fmaxf(b, 0.f);
    }
    __syncthreads();

    if (tid < 10) {
        float c = fc3_b[tid];
#pragma unroll 8
        for (int k = 0; k < DMODEL / 2; k++)
            c = fmaf(sm2[k], fc3_w[k * 10 + tid], c);
        out[g * 10 + tid] = c;
    }
}

// ---------------- eager module load (pre-checkpoint; no alloc APIs) -------------
namespace {
struct EagerLoad {
    EagerLoad() {
        void* p;
        cudaGetSymbolAddress(&p, g_x16);   cudaGetSymbolAddress(&p, g_h1);
        cudaGetSymbolAddress(&p, g_h2);
        cudaGetSymbolAddress(&p, g_f16a);  cudaGetSymbolAddress(&p, g_f16b);
        cudaGetSymbolAddress(&p, g_w16);
        cudaGetSymbolAddress(&p, g_dinv);  cudaGetSymbolAddress(&p, g_deg);
        cudaGetSymbolAddress(&p, g_rowptr); cudaGetSymbolAddress(&p, g_fill);
        cudaGetSymbolAddress(&p, g_csrc);
        cudaGetSymbolAddress(&p, g_blocksum); cudaGetSymbolAddress(&p, g_blockoff);
        cudaGetSymbolAddress(&p, g_pool);  cudaGetSymbolAddress(&p, g_is64);
        cudaFuncAttributes a;
        cudaFuncGetAttributes(&a, (const void*)detect_dtype);
        cudaFuncGetAttributes(&a, (const void*)init_misc);
        cudaFuncGetAttributes(&a, (const void*)count_deg);
        cudaFuncGetAttributes(&a, (const void*)scan_block_sums);
        cudaFuncGetAttributes(&a, (const void*)scan_offsets);
        cudaFuncGetAttributes(&a, (const void*)scan_final);
        cudaFuncGetAttributes(&a, (const void*)build_csr);
        cudaFuncGetAttributes(&a, (const void*)cvt_scale_half);
        cudaFuncGetAttributes(&a, (const void*)cvt_weights);
        cudaFuncGetAttributes(&a, (const void*)prop_gather<FIN, 2, 0, 0>);
        cudaFuncGetAttributes(&a, (const void*)prop_gather<FIN, 1, 0, 0>);
        cudaFuncGetAttributes(&a, (const void*)prop_gather<DMODEL, 1, 1, 0>);
        cudaFuncGetAttributes(&a, (const void*)prop_gather<DMODEL, 1, 1, 1>);
        cudaFuncGetAttributes(&a, (const void*)hgemm128);
        cudaFuncGetAttributes(&a, (const void*)mlp_head);
        cudaFuncSetAttribute((const void*)hgemm128,
                             cudaFuncAttributeMaxDynamicSharedMemorySize, HG_SMEM);
        cudaDeviceSynchronize();
    }
};
EagerLoad eager_load_instance;
}  // namespace

// ---------------- launch --------------------------------------------------------
static inline int cdiv(long long a, long long b) { return (int)((a + b - 1) / b); }

extern "C" void kernel_launch(void* const* d_in, const int* in_sizes, int n_in,
                              void* d_out, int out_size) {
    const float* x     = (const float*)d_in[0];
    const void*  ei    = d_in[1];
    const void*  batch = d_in[2];
    const float* sg_w  = (const float*)d_in[3];
    const float* sg_b  = (const float*)d_in[4];
    const float* gcn_w = (const float*)d_in[5];
    const float* gcn_b = (const float*)d_in[6];
    const float* fc1_w = (const float*)d_in[7];
    const float* fc1_b = (const float*)d_in[8];
    const float* fc2_w = (const float*)d_in[9];
    const float* fc2_b = (const float*)d_in[10];
    const float* fc3_w = (const float*)d_in[11];
    const float* fc3_b = (const float*)d_in[12];

    int n = in_sizes[0] / FIN;
    int e = in_sizes[1] / 2;
    int G = out_size / 10;

    __half *x16, *h1, *h2, *f16a, *f16b, *w16;
    cudaGetSymbolAddress((void**)&x16,  g_x16);
    cudaGetSymbolAddress((void**)&h1,   g_h1);
    cudaGetSymbolAddress((void**)&h2,   g_h2);
    cudaGetSymbolAddress((void**)&f16a, g_f16a);
    cudaGetSymbolAddress((void**)&f16b, g_f16b);
    cudaGetSymbolAddress((void**)&w16,  g_w16);

    // ---- CSR build + weight conversion + pool zeroing ----
    detect_dtype<<<1, 1024>>>((const unsigned int*)ei);
    init_misc<<<cdiv(n, 256), 256>>>(n);
    count_deg<<<cdiv(e, 256), 256>>>(ei, e);
    int nb = cdiv(n, 1024);
    scan_block_sums<<<nb, 1024>>>(n);
    scan_offsets<<<1, 32>>>(nb, n);
    scan_final<<<nb, 1024>>>(n);
    build_csr<<<cdiv(e, 256), 256>>>(ei, e);
    cvt_weights<<<cdiv(128 * 256 + 3 * 256 * 256, 256), 256>>>(sg_w, gcn_w);

    // ---- SGConv hops (F=128), factored normalization ----
    cvt_scale_half<<<cdiv((long long)n * FIN / 4, 256), 256>>>(x, x16, n);
    prop_gather<FIN, 2, 0, 0><<<cdiv((long long)n * 16, 256), 256>>>(
        x16, h1, nullptr, nullptr, n);
    prop_gather<FIN, 1, 0, 0><<<cdiv((long long)n * 16, 256), 256>>>(
        h1, h2, nullptr, nullptr, n);

    // h = relu(h2 @ sg_w + sg_b) -> f16b  (fp16 HMMA, 3-stage pipeline)
    hgemm128<<<dim3(DMODEL / 128, cdiv(n, 128)), 256, HG_SMEM>>>(
        h2, w16, sg_b, f16b, n, FIN, DMODEL, 1, 0);

    // ---- 3x GCN layers; last propagate fuses global_add_pool ----
    for (int i = 0; i < 3; i++) {
        hgemm128<<<dim3(DMODEL / 128, cdiv(n, 128)), 256, HG_SMEM>>>(
            f16b, w16 + 128 * 256 + (size_t)i * 65536, nullptr, f16a,
            n, DMODEL, DMODEL, 0, 1);
        if (i < 2) {
            prop_gather<DMODEL, 1, 1, 0><<<cdiv((long long)n * 16, 256), 256>>>(
                f16a, f16b, gcn_b + (size_t)i * DMODEL, nullptr, n);
        } else {
            prop_gather<DMODEL, 1, 1, 1><<<cdiv((long long)n * 16, 256), 256>>>(
                f16a, nullptr, gcn_b + (size_t)i * DMODEL, batch, n);
        }
    }

    // ---- fused MLP head (exact fp32) ----
    mlp_head<<<G, DMODEL>>>(fc1_w, fc1_b, fc2_w, fc2_b, fc3_w, fc3_b,
                            (float*)d_out);
}

// round 17
// speedup vs baseline: 1.0890x; 1.0890x over previous
#include <cuda_runtime.h>
#include <cuda_fp16.h>
#include <cstdint>

#define MAXN 50000
#define MAXN_PAD 50176              // 128-aligned: GEMM tiles read padded rows unguarded
#define MAXE 1600000
#define DMODEL 256
#define FIN 128
#define NGRAPH 128

#define HG_PAD 40                   // smem row stride (halves): 80B, conflict-friendly
#define HG_STAGE (128 * HG_PAD)
#define HG_SMEM (3 * 2 * HG_STAGE * 2)  // 61440 B: 3 stages x (A+B) x fp16

// ---------------- device scratch (allocation-free rule: __device__ globals) ----
__device__ __half g_x16[(size_t)MAXN_PAD * FIN];
__device__ __half g_h1[(size_t)MAXN_PAD * FIN];
__device__ __half g_h2[(size_t)MAXN_PAD * FIN];
__device__ __half g_f16a[(size_t)MAXN_PAD * DMODEL];
__device__ __half g_f16b[(size_t)MAXN_PAD * DMODEL];
__device__ __half g_w16[128 * 256 + 3 * 256 * 256];  // sg_w^T, gcn_w[i]^T, fp16 [n][k]
__device__ float  g_dinv[MAXN];
__device__ int    g_deg[MAXN];
__device__ int    g_rowptr[MAXN + 1];
__device__ int    g_fill[MAXN];
__device__ int    g_csrc[MAXE];       // CSR (by dst): src index only (weights factored)
__device__ int    g_blocksum[64];
__device__ int    g_blockoff[64];
__device__ float  g_pool[NGRAPH * DMODEL];
__device__ int    g_is64;

// ---------------- dtype sniffing (int64 vs int32 edge_index) -------------------
__global__ void detect_dtype(const unsigned int* __restrict__ words) {
    __shared__ int nz;
    if (threadIdx.x == 0) nz = 0;
    __syncthreads();
    if (words[2 * threadIdx.x + 1] != 0u) atomicOr(&nz, 1);
    __syncthreads();
    if (threadIdx.x == 0) g_is64 = (nz == 0) ? 1 : 0;
}

__device__ __forceinline__ int ld_idx(const void* p, long long i, int is64) {
    return is64 ? (int)((const long long*)p)[i] : ((const int*)p)[i];
}

// ---------------- edge preprocessing / CSR build --------------------------------
__global__ void init_misc(int n) {
    int i = blockIdx.x * blockDim.x + threadIdx.x;
    if (i < n) g_deg[i] = 1;
    if (i < NGRAPH * DMODEL) g_pool[i] = 0.f;
}

// Two edges per thread: paired loads batch; half the blocks.
__global__ void count_deg(const void* __restrict__ ei, int e) {
    int i = (blockIdx.x * blockDim.x + threadIdx.x) * 2;
    if (i >= e) return;
    int is64 = g_is64;
    int d0 = ld_idx(ei, (long long)e + i, is64);
    int d1 = (i + 1 < e) ? ld_idx(ei, (long long)e + i + 1, is64) : -1;
    atomicAdd(&g_deg[d0], 1);
    if (d1 >= 0) atomicAdd(&g_deg[d1], 1);
}

__global__ void scan_block_sums(int n) {
    __shared__ int sm[1024];
    int i = blockIdx.x * 1024 + threadIdx.x;
    int deg = (i < n) ? g_deg[i] : 1;
    if (i < n) g_dinv[i] = rsqrtf((float)deg);
    sm[threadIdx.x] = (i < n) ? (deg - 1) : 0;
    __syncthreads();
    for (int off = 512; off > 0; off >>= 1) {
        if (threadIdx.x < off) sm[threadIdx.x] += sm[threadIdx.x + off];
        __syncthreads();
    }
    if (threadIdx.x == 0) g_blocksum[blockIdx.x] = sm[0];
}

__global__ void scan_offsets(int nblocks, int n) {
    if (threadIdx.x == 0) {
        int c = 0;
        for (int b = 0; b < nblocks; b++) { g_blockoff[b] = c; c += g_blocksum[b]; }
        g_rowptr[n] = c;
    }
}

__global__ void scan_final(int n) {
    __shared__ int sm[1024];
    int i = blockIdx.x * 1024 + threadIdx.x;
    int v = (i < n) ? (g_deg[i] - 1) : 0;
    sm[threadIdx.x] = v;
    __syncthreads();
    for (int off = 1; off < 1024; off <<= 1) {
        int t = (threadIdx.x >= off) ? sm[threadIdx.x - off] : 0;
        __syncthreads();
        sm[threadIdx.x] += t;
        __syncthreads();
    }
    if (i < n) {
        int excl = g_blockoff[blockIdx.x] + sm[threadIdx.x] - v;
        g_rowptr[i] = excl;
        g_fill[i] = excl;
    }
}

// Two edges per thread.
__global__ void build_csr(const void* __restrict__ ei, int e) {
    int i = (blockIdx.x * blockDim.x + threadIdx.x) * 2;
    if (i >= e) return;
    int is64 = g_is64;
    int s0 = ld_idx(ei, i, is64);
    int d0 = ld_idx(ei, (long long)e + i, is64);
    int has1 = (i + 1 < e);
    int s1 = 0, d1 = 0;
    if (has1) {
        s1 = ld_idx(ei, i + 1, is64);
        d1 = ld_idx(ei, (long long)e + i + 1, is64);
    }
    int pos0 = atomicAdd(&g_fill[d0], 1);
    g_csrc[pos0] = s0;
    if (has1) {
        int pos1 = atomicAdd(&g_fill[d1], 1);
        g_csrc[pos1] = s1;
    }
}

// ---------------- fp32 -> fp16 converts -----------------------------------------
__global__ void cvt_scale_half(const float* __restrict__ x, __half* __restrict__ o,
                               int n) {
    long long i = (long long)blockIdx.x * blockDim.x + threadIdx.x;
    if (i >= (long long)n * (FIN / 4)) return;
    int v = (int)(i >> 5);
    float dv = g_dinv[v];
    float4 t = ((const float4*)x)[i];
    __half2 a = __floats2half2_rn(dv * t.x, dv * t.y);
    __half2 b = __floats2half2_rn(dv * t.z, dv * t.w);
    uint2 u;
    u.x = *(unsigned int*)&a;
    u.y = *(unsigned int*)&b;
    ((uint2*)o)[i] = u;
}

__global__ void cvt_weights(const float* __restrict__ sg_w,
                            const float* __restrict__ gcn_w) {
    int idx = blockIdx.x * blockDim.x + threadIdx.x;
    if (idx < 128 * 256) {
        int k = idx >> 8, nn = idx & 255;
        g_w16[nn * 128 + k] = __float2half_rn(sg_w[idx]);
    } else if (idx < 128 * 256 + 3 * 256 * 256) {
        int j = idx - 128 * 256;
        int i = j >> 16, rem = j & 65535;
        int k = rem >> 8, nn = rem & 255;
        g_w16[128 * 256 + i * 65536 + nn * 256 + k] = __float2half_rn(gcn_w[j]);
    }
}

// ---------------- fused gather propagation (R14 shape: proven fastest) ----------
// Input rows pre-scaled: in'[v] = dinv[v]*in[v]. acc = in'[node] + sum in'[src].
// POST=1: scale dinv; POST=2: scale dinv^2. POOL=1: red.add into g_pool[batch].
template <int F, int POST, int RELUB, int POOL>
__global__ __launch_bounds__(256) void prop_gather(
    const __half* __restrict__ x, __half* __restrict__ out,
    const float* __restrict__ bias, const void* __restrict__ batch, int n) {
    constexpr int SUB = F / 8;             // 16 (F=128) or 32 (F=256)
    int gt = blockIdx.x * blockDim.x + threadIdx.x;
    int node = gt / SUB;
    if (node >= n) return;
    int sl = threadIdx.x & (SUB - 1);
    unsigned mask = (SUB == 32) ? 0xffffffffu
                                : (0xffffu << (threadIdx.x & 16));
    const uint4* __restrict__ xr = (const uint4*)x;

    float acc[8];

#define GATHER_ROW(srow)                                                         \
    do {                                                                         \
        uint4 u_ = __ldg(xr + (size_t)(srow) * (F / 8) + sl);                    \
        float2 f0_ = __half22float2(*(__half2*)&u_.x);                           \
        float2 f1_ = __half22float2(*(((__half2*)&u_.x) + 1));                   \
        float2 f2_ = __half22float2(*(__half2*)&u_.z);                           \
        float2 f3_ = __half22float2(*(((__half2*)&u_.z) + 1));                   \
        acc[0] += f0_.x; acc[1] += f0_.y; acc[2] += f1_.x; acc[3] += f1_.y;      \
        acc[4] += f2_.x; acc[5] += f2_.y; acc[6] += f3_.x; acc[7] += f3_.y;      \
    } while (0)

#pragma unroll
    for (int q = 0; q < 8; q++) acc[q] = 0.f;
    GATHER_ROW(node);  // self-loop (already pre-scaled)

    int beg = g_rowptr[node], end = g_rowptr[node + 1];
    int b = beg;
    for (; b + SUB <= end; b += SUB) {
        int sj = __ldg(g_csrc + b + sl);
#pragma unroll
        for (int k = 0; k < SUB; k++) {
            int s = __shfl_sync(mask, sj, k, SUB);
            GATHER_ROW(s);
        }
    }
    int rem = end - b;
    if (rem > 0) {
        int sj = 0;
        if (sl < rem) sj = __ldg(g_csrc + b + sl);
        for (int k = 0; k < rem; k++) {
            int s = __shfl_sync(mask, sj, k, SUB);
            GATHER_ROW(s);
        }
    }
#undef GATHER_ROW

    float dv = g_dinv[node];
    float scale = (POST == 2) ? dv * dv : dv;
#pragma unroll
    for (int q = 0; q < 8; q++) acc[q] *= scale;

    if (RELUB) {
        float4 b0 = *(const float4*)(bias + sl * 8);
        float4 b1 = *(const float4*)(bias + sl * 8 + 4);
        acc[0] = fmaxf(acc[0] + b0.x, 0.f); acc[1] = fmaxf(acc[1] + b0.y, 0.f);
        acc[2] = fmaxf(acc[2] + b0.z, 0.f); acc[3] = fmaxf(acc[3] + b0.w, 0.f);
        acc[4] = fmaxf(acc[4] + b1.x, 0.f); acc[5] = fmaxf(acc[5] + b1.y, 0.f);
        acc[6] = fmaxf(acc[6] + b1.z, 0.f); acc[7] = fmaxf(acc[7] + b1.w, 0.f);
    }

    if (POOL) {
        int g = ld_idx(batch, node, g_is64);
        float* dst = g_pool + (size_t)g * DMODEL + sl * 8;
        asm volatile("red.global.add.v4.f32 [%0], {%1, %2, %3, %4};"
                     :: "l"(dst), "f"(acc[0]), "f"(acc[1]), "f"(acc[2]), "f"(acc[3])
                     : "memory");
        asm volatile("red.global.add.v4.f32 [%0], {%1, %2, %3, %4};"
                     :: "l"(dst + 4), "f"(acc[4]), "f"(acc[5]), "f"(acc[6]), "f"(acc[7])
                     : "memory");
    } else {
        uint4 u;
        __half2 h0 = __floats2half2_rn(acc[0], acc[1]);
        __half2 h1 = __floats2half2_rn(acc[2], acc[3]);
        __half2 h2 = __floats2half2_rn(acc[4], acc[5]);
        __half2 h3 = __floats2half2_rn(acc[6], acc[7]);
        u.x = *(unsigned int*)&h0; u.y = *(unsigned int*)&h1;
        u.z = *(unsigned int*)&h2; u.w = *(unsigned int*)&h3;
        ((uint4*)out)[(size_t)node * (F / 8) + sl] = u;
    }
}

// ---------------- cp.async helpers ----------------------------------------------
__device__ __forceinline__ void cp_async16(void* smem, const void* gmem) {
    unsigned saddr;
    asm("{ .reg .u64 t; cvta.to.shared.u64 t, %1; cvt.u32.u64 %0, t; }"
        : "=r"(saddr) : "l"(smem));
    asm volatile("cp.async.cg.shared.global [%0], [%1], 16;"
                 :: "r"(saddr), "l"(gmem) : "memory");
}

// ---------------- fp16 HMMA GEMM, 3-stage cp.async pipeline (dynamic smem) ------
__global__ __launch_bounds__(256) void hgemm128(
    const __half* __restrict__ A, const __half* __restrict__ Bt,
    const float* __restrict__ bias, __half* __restrict__ C,
    int M, int K, int N, int relu, int scale) {
    extern __shared__ __align__(16) __half smem[];
    __half* Asm = smem;
    __half* Bsm = smem + 3 * HG_STAGE;
#define AS(st, r, c) Asm[(st) * HG_STAGE + (r) * HG_PAD + (c)]
#define BS(st, r, c) Bsm[(st) * HG_STAGE + (r) * HG_PAD + (c)]
    int tid = threadIdx.x;
    int warp = tid >> 5, lane = tid & 31;
    int wm = warp >> 1, wn = warp & 1;
    int row0 = blockIdx.y * 128, col0 = blockIdx.x * 128;
    int gid = lane >> 2, tig = lane & 3;

    float acc[2][8][4];
#pragma unroll
    for (int i = 0; i < 2; i++)
#pragma unroll
        for (int j = 0; j < 8; j++)
#pragma unroll
            for (int q = 0; q < 4; q++) acc[i][j][q] = 0.f;

    int fr = tid >> 2, fc = (tid & 3) * 8;
    const __half* Ap = A + (size_t)(row0 + fr) * K + fc;
    const __half* Ap2 = A + (size_t)(row0 + fr + 64) * K + fc;
    const __half* Bp = Bt + (size_t)(col0 + fr) * K + fc;
    const __half* Bp2 = Bt + (size_t)(col0 + fr + 64) * K + fc;

    int T = K >> 5;
#pragma unroll
    for (int s = 0; s < 2; s++) {
        if (s < T) {
            int kk = s * 32;
            cp_async16(&AS(s, fr, fc), Ap + kk);
            cp_async16(&AS(s, fr + 64, fc), Ap2 + kk);
            cp_async16(&BS(s, fr, fc), Bp + kk);
            cp_async16(&BS(s, fr + 64, fc), Bp2 + kk);
        }
        asm volatile("cp.async.commit_group;");
    }

    for (int t = 0; t < T; t++) {
        if (t + 2 < T) {
            int k2 = (t + 2) * 32;
            int st2 = (t + 2) % 3;
            cp_async16(&AS(st2, fr, fc), Ap + k2);
            cp_async16(&AS(st2, fr + 64, fc), Ap2 + k2);
            cp_async16(&BS(st2, fr, fc), Bp + k2);
            cp_async16(&BS(st2, fr + 64, fc), Bp2 + k2);
        }
        asm volatile("cp.async.commit_group;");
        asm volatile("cp.async.wait_group 2;");
        __syncthreads();
        int st = t % 3;
#pragma unroll
        for (int ks = 0; ks < 2; ks++) {
            int kk = ks * 16;
            unsigned int af[2][4];
#pragma unroll
            for (int mt = 0; mt < 2; mt++) {
                int r = wm * 32 + mt * 16 + gid;
                af[mt][0] = *(unsigned int*)&AS(st, r, kk + 2 * tig);
                af[mt][1] = *(unsigned int*)&AS(st, r + 8, kk + 2 * tig);
                af[mt][2] = *(unsigned int*)&AS(st, r, kk + 2 * tig + 8);
                af[mt][3] = *(unsigned int*)&AS(st, r + 8, kk + 2 * tig + 8);
            }
            unsigned int bf[8][2];
#pragma unroll
            for (int nt = 0; nt < 8; nt++) {
                int c = wn * 64 + nt * 8 + gid;
                bf[nt][0] = *(unsigned int*)&BS(st, c, kk + 2 * tig);
                bf[nt][1] = *(unsigned int*)&BS(st, c, kk + 2 * tig + 8);
            }
#pragma unroll
            for (int mt = 0; mt < 2; mt++)
#pragma unroll
                for (int nt = 0; nt < 8; nt++) {
                    asm volatile(
                        "mma.sync.aligned.m16n8k16.row.col.f32.f16.f16.f32 "
                        "{%0,%1,%2,%3}, {%4,%5,%6,%7}, {%8,%9}, {%0,%1,%2,%3};"
                        : "+f"(acc[mt][nt][0]), "+f"(acc[mt][nt][1]),
                          "+f"(acc[mt][nt][2]), "+f"(acc[mt][nt][3])
                        : "r"(af[mt][0]), "r"(af[mt][1]), "r"(af[mt][2]), "r"(af[mt][3]),
                          "r"(bf[nt][0]), "r"(bf[nt][1]));
                }
        }
        __syncthreads();
    }
#undef AS
#undef BS

#pragma unroll
    for (int mt = 0; mt < 2; mt++) {
        int r1 = row0 + wm * 32 + mt * 16 + gid;
        int r2 = r1 + 8;
        float s1 = 1.f, s2 = 1.f;
        if (scale) {
            s1 = (r1 < M) ? g_dinv[r1] : 0.f;
            s2 = (r2 < M) ? g_dinv[r2] : 0.f;
        }
#pragma unroll
        for (int nt = 0; nt < 8; nt++) {
            int c = col0 + wn * 64 + nt * 8 + 2 * tig;
            float bx = 0.f, by = 0.f;
            if (bias) { bx = bias[c]; by = bias[c + 1]; }
            float2 v1 = make_float2((acc[mt][nt][0] + bx) * s1, (acc[mt][nt][1] + by) * s1);
            float2 v2 = make_float2((acc[mt][nt][2] + bx) * s2, (acc[mt][nt][3] + by) * s2);
            if (relu) {
                v1.x = fmaxf(v1.x, 0.f); v1.y = fmaxf(v1.y, 0.f);
                v2.x = fmaxf(v2.x, 0.f); v2.y = fmaxf(v2.y, 0.f);
            }
            if (r1 < M) *(__half2*)(C + (size_t)r1 * N + c) = __floats2half2_rn(v1.x, v1.y);
            if (r2 < M) *(__half2*)(C + (size_t)r2 * N + c) = __floats2half2_rn(v2.x, v2.y);
        }
    }
}

// ---------------- fused MLP head (exact fp32): pool -> fc1 -> fc2 -> fc3 --------
__global__ __launch_bounds__(256) void mlp_head(
    const float* __restrict__ fc1_w, const float* __restrict__ fc1_b,
    const float* __restrict__ fc2_w, const float* __restrict__ fc2_b,
    const float* __restrict__ fc3_w, const float* __restrict__ fc3_b,
    float* __restrict__ out) {
    __shared__ float sp[DMODEL];
    __shared__ float sm1[DMODEL];
    __shared__ float sm2[DMODEL / 2];
    int g = blockIdx.x;
    int tid = threadIdx.x;

    sp[tid] = g_pool[g * DMODEL + tid];
    __syncthreads();

    float a = fc1_b[tid];
#pragma unroll 8
    for (int k = 0; k < DMODEL; k++)
        a = fmaf(sp[k], fc1_w[k * DMODEL + tid], a);
    sm1[tid] = fmaxf(a, 0.f);
    __syncthreads();

    if (tid < DMODEL / 2) {
        float b = fc2_b[tid];
#pragma unroll 8
        for (int k = 0; k < DMODEL; k++)
            b = fmaf(sm1[k], fc2_w[k * (DMODEL / 2) + tid], b);
        sm2[tid] = fmaxf(b, 0.f);
    }
    __syncthreads();

    if (tid < 10) {
        float c = fc3_b[tid];
#pragma unroll 8
        for (int k = 0; k < DMODEL / 2; k++)
            c = fmaf(sm2[k], fc3_w[k * 10 + tid], c);
        out[g * 10 + tid] = c;
    }
}

// ---------------- eager module load (pre-checkpoint; no alloc APIs) -------------
namespace {
struct EagerLoad {
    EagerLoad() {
        void* p;
        cudaGetSymbolAddress(&p, g_x16);   cudaGetSymbolAddress(&p, g_h1);
        cudaGetSymbolAddress(&p, g_h2);
        cudaGetSymbolAddress(&p, g_f16a);  cudaGetSymbolAddress(&p, g_f16b);
        cudaGetSymbolAddress(&p, g_w16);
        cudaGetSymbolAddress(&p, g_dinv);  cudaGetSymbolAddress(&p, g_deg);
        cudaGetSymbolAddress(&p, g_rowptr); cudaGetSymbolAddress(&p, g_fill);
        cudaGetSymbolAddress(&p, g_csrc);
        cudaGetSymbolAddress(&p, g_blocksum); cudaGetSymbolAddress(&p, g_blockoff);
        cudaGetSymbolAddress(&p, g_pool);  cudaGetSymbolAddress(&p, g_is64);
        cudaFuncAttributes a;
        cudaFuncGetAttributes(&a, (const void*)detect_dtype);
        cudaFuncGetAttributes(&a, (const void*)init_misc);
        cudaFuncGetAttributes(&a, (const void*)count_deg);
        cudaFuncGetAttributes(&a, (const void*)scan_block_sums);
        cudaFuncGetAttributes(&a, (const void*)scan_offsets);
        cudaFuncGetAttributes(&a, (const void*)scan_final);
        cudaFuncGetAttributes(&a, (const void*)build_csr);
        cudaFuncGetAttributes(&a, (const void*)cvt_scale_half);
        cudaFuncGetAttributes(&a, (const void*)cvt_weights);
        cudaFuncGetAttributes(&a, (const void*)prop_gather<FIN, 2, 0, 0>);
        cudaFuncGetAttributes(&a, (const void*)prop_gather<FIN, 1, 0, 0>);
        cudaFuncGetAttributes(&a, (const void*)prop_gather<DMODEL, 1, 1, 0>);
        cudaFuncGetAttributes(&a, (const void*)prop_gather<DMODEL, 1, 1, 1>);
        cudaFuncGetAttributes(&a, (const void*)hgemm128);
        cudaFuncGetAttributes(&a, (const void*)mlp_head);
        cudaFuncSetAttribute((const void*)hgemm128,
                             cudaFuncAttributeMaxDynamicSharedMemorySize, HG_SMEM);
        cudaDeviceSynchronize();
    }
};
EagerLoad eager_load_instance;
}  // namespace

// ---------------- launch --------------------------------------------------------
static inline int cdiv(long long a, long long b) { return (int)((a + b - 1) / b); }

extern "C" void kernel_launch(void* const* d_in, const int* in_sizes, int n_in,
                              void* d_out, int out_size) {
    const float* x     = (const float*)d_in[0];
    const void*  ei    = d_in[1];
    const void*  batch = d_in[2];
    const float* sg_w  = (const float*)d_in[3];
    const float* sg_b  = (const float*)d_in[4];
    const float* gcn_w = (const float*)d_in[5];
    const float* gcn_b = (const float*)d_in[6];
    const float* fc1_w = (const float*)d_in[7];
    const float* fc1_b = (const float*)d_in[8];
    const float* fc2_w = (const float*)d_in[9];
    const float* fc2_b = (const float*)d_in[10];
    const float* fc3_w = (const float*)d_in[11];
    const float* fc3_b = (const float*)d_in[12];

    int n = in_sizes[0] / FIN;
    int e = in_sizes[1] / 2;
    int G = out_size / 10;

    __half *x16, *h1, *h2, *f16a, *f16b, *w16;
    cudaGetSymbolAddress((void**)&x16,  g_x16);
    cudaGetSymbolAddress((void**)&h1,   g_h1);
    cudaGetSymbolAddress((void**)&h2,   g_h2);
    cudaGetSymbolAddress((void**)&f16a, g_f16a);
    cudaGetSymbolAddress((void**)&f16b, g_f16b);
    cudaGetSymbolAddress((void**)&w16,  g_w16);

    // ---- CSR build + weight conversion + pool zeroing ----
    detect_dtype<<<1, 1024>>>((const unsigned int*)ei);
    init_misc<<<cdiv(n, 256), 256>>>(n);
    count_deg<<<cdiv(cdiv(e, 2), 256), 256>>>(ei, e);
    int nb = cdiv(n, 1024);
    scan_block_sums<<<nb, 1024>>>(n);
    scan_offsets<<<1, 32>>>(nb, n);
    scan_final<<<nb, 1024>>>(n);
    build_csr<<<cdiv(cdiv(e, 2), 256), 256>>>(ei, e);
    cvt_weights<<<cdiv(128 * 256 + 3 * 256 * 256, 256), 256>>>(sg_w, gcn_w);

    // ---- SGConv hops (F=128), factored normalization ----
    cvt_scale_half<<<cdiv((long long)n * FIN / 4, 256), 256>>>(x, x16, n);
    prop_gather<FIN, 2, 0, 0><<<cdiv((long long)n * 16, 256), 256>>>(
        x16, h1, nullptr, nullptr, n);
    prop_gather<FIN, 1, 0, 0><<<cdiv((long long)n * 16, 256), 256>>>(
        h1, h2, nullptr, nullptr, n);

    // h = relu(h2 @ sg_w + sg_b) -> f16b  (fp16 HMMA, 3-stage pipeline)
    hgemm128<<<dim3(DMODEL / 128, cdiv(n, 128)), 256, HG_SMEM>>>(
        h2, w16, sg_b, f16b, n, FIN, DMODEL, 1, 0);

    // ---- 3x GCN layers; last propagate fuses global_add_pool ----
    for (int i = 0; i < 3; i++) {
        hgemm128<<<dim3(DMODEL / 128, cdiv(n, 128)), 256, HG_SMEM>>>(
            f16b, w16 + 128 * 256 + (size_t)i * 65536, nullptr, f16a,
            n, DMODEL, DMODEL, 0, 1);
        if (i < 2) {
            prop_gather<DMODEL, 1, 1, 0><<<cdiv((long long)n * 32, 256), 256>>>(
                f16a, f16b, gcn_b + (size_t)i * DMODEL, nullptr, n);
        } else {
            prop_gather<DMODEL, 1, 1, 1><<<cdiv((long long)n * 32, 256), 256>>>(
                f16a, nullptr, gcn_b + (size_t)i * DMODEL, batch, n);
        }
    }

    // ---- fused MLP head (exact fp32) ----
    mlp_head<<<G, DMODEL>>>(fc1_w, fc1_b, fc2_w, fc2_b, fc3_w, fc3_b,
                            (float*)d_out);
}